// round 1
// baseline (speedup 1.0000x reference)
#include <cuda_runtime.h>
#include <math.h>
#include <stdint.h>

#define NB 128
#define NA_MAX 500000

// Scratch (allocation-free: __device__ globals)
__device__ float  g_sym[NB * 9];     // symmetrized strain per batch
__device__ float  g_cell[NB * 9];    // cell + cell @ sym
__device__ float4 g_atom[NA_MAX];    // strained pos + batch (bit-cast) per atom
__device__ int    g_is64;            // 1 if edge_index/batch are int64, else int32

// ---------------------------------------------------------------------------
// Kernel 0: dtype detection + strain symmetrization + cell update (1 block)
// ---------------------------------------------------------------------------
__global__ void prep_kernel(const float* __restrict__ cell,
                            const float* __restrict__ strain,
                            const unsigned* __restrict__ eidx_words) {
    __shared__ int s_any;
    int tid = threadIdx.x;
    if (tid == 0) s_any = 0;
    __syncthreads();

    // If indices are int64, all odd 32-bit words are 0 (indices < 2^31, nonneg).
    // If int32, odd words are random indices in [0, 500000) — virtually never all 0.
    int any = 0;
    for (int i = tid; i < 1024; i += blockDim.x)
        if (eidx_words[2 * i + 1] != 0u) any = 1;
    if (any) atomicOr(&s_any, 1);

    // sym = 0.5 * (strain + strain^T) per batch
    for (int i = tid; i < NB * 9; i += blockDim.x) {
        int b = i / 9, r = (i % 9) / 3, c = i % 3;
        g_sym[i] = 0.5f * (strain[b * 9 + r * 3 + c] + strain[b * 9 + c * 3 + r]);
    }
    __syncthreads();

    if (tid == 0) g_is64 = s_any ? 0 : 1;

    // cell_new = cell + cell @ sym
    for (int i = tid; i < NB * 9; i += blockDim.x) {
        int b = i / 9, r = (i % 9) / 3, c = i % 3;
        float acc = cell[b * 9 + r * 3 + c];
#pragma unroll
        for (int k = 0; k < 3; k++)
            acc += cell[b * 9 + r * 3 + k] * g_sym[b * 9 + k * 3 + c];
        g_cell[i] = acc;
    }
}

// ---------------------------------------------------------------------------
// Kernel 1: per-atom strained position, packed with batch into float4
// ---------------------------------------------------------------------------
__global__ void atom_kernel(const float* __restrict__ pos,
                            const void* __restrict__ batch,
                            int n_atoms) {
    int i = blockIdx.x * blockDim.x + threadIdx.x;
    if (i >= n_atoms) return;

    int b;
    if (g_is64) b = (int)((const long long*)batch)[i];
    else        b = ((const int*)batch)[i];

    float px = pos[3 * i], py = pos[3 * i + 1], pz = pos[3 * i + 2];
    const float* S = &g_sym[b * 9];
    // new_j = p_j + sum_i p_i * sym[i][j]
    float nx = px + px * S[0] + py * S[3] + pz * S[6];
    float ny = py + px * S[1] + py * S[4] + pz * S[7];
    float nz = pz + px * S[2] + py * S[5] + pz * S[8];
    g_atom[i] = make_float4(nx, ny, nz, __int_as_float(b));
}

// ---------------------------------------------------------------------------
// Kernel 2: edge vectors + lengths (HBM streaming + L2 gathers)
// ---------------------------------------------------------------------------
__global__ void edge_kernel(const void* __restrict__ eidx,
                            const float* __restrict__ cshift,
                            float* __restrict__ out,
                            long long E) {
    __shared__ float sC[NB * 9];
    for (int i = threadIdx.x; i < NB * 9; i += blockDim.x)
        sC[i] = g_cell[i];
    __syncthreads();

    long long e = (long long)blockIdx.x * blockDim.x + threadIdx.x;
    if (e >= E) return;

    long long src, dst;
    if (g_is64) {
        const long long* p = (const long long*)eidx;
        src = p[e];
        dst = p[E + e];
    } else {
        const int* p = (const int*)eidx;
        src = (long long)p[e];
        dst = (long long)p[E + e];
    }

    float4 as = g_atom[src];   // 16B aligned gather, L2-resident (8 MB table)
    float4 ad = g_atom[dst];
    int b = __float_as_int(as.w);

    float s0 = cshift[3 * e], s1 = cshift[3 * e + 1], s2 = cshift[3 * e + 2];
    const float* C = &sC[b * 9];

    float ex = ad.x - as.x + s0 * C[0] + s1 * C[3] + s2 * C[6];
    float ey = ad.y - as.y + s0 * C[1] + s1 * C[4] + s2 * C[7];
    float ez = ad.z - as.z + s0 * C[2] + s1 * C[5] + s2 * C[8];

    out[3 * e]     = ex;
    out[3 * e + 1] = ey;
    out[3 * e + 2] = ez;
    out[3 * E + e] = sqrtf(ex * ex + ey * ey + ez * ez);
}

// ---------------------------------------------------------------------------
// Launch: prep -> atoms -> edges (sequential on default stream, graph-capturable)
// ---------------------------------------------------------------------------
extern "C" void kernel_launch(void* const* d_in, const int* in_sizes, int n_in,
                              void* d_out, int out_size) {
    const float* pos    = (const float*)d_in[0];   // [N_ATOMS, 3]
    const float* cell   = (const float*)d_in[1];   // [NB, 3, 3]
    const float* cshift = (const float*)d_in[2];   // [E, 3]
    const void*  eidx   = d_in[3];                 // [2, E] int32 or int64
    const void*  batch  = d_in[4];                 // [N_ATOMS] int32 or int64
    const float* strain = (const float*)d_in[5];   // [NB, 3, 3]

    int n_atoms   = in_sizes[0] / 3;
    long long E   = (long long)in_sizes[3] / 2;

    prep_kernel<<<1, 256>>>(cell, strain, (const unsigned*)eidx);

    int ablocks = (n_atoms + 255) / 256;
    atom_kernel<<<ablocks, 256>>>(pos, batch, n_atoms);

    long long eblocks = (E + 255) / 256;
    edge_kernel<<<(unsigned)eblocks, 256>>>(eidx, cshift, (float*)d_out, E);
}

// round 2
// speedup vs baseline: 1.1068x; 1.1068x over previous
#include <cuda_runtime.h>
#include <math.h>
#include <stdint.h>

#define NB 128
#define NA_MAX 500000

// Scratch (allocation-free: __device__ globals)
__device__ float  g_cell[NB * 9];    // cell + cell @ sym (written by atom block 0)
__device__ float4 g_atom[NA_MAX];    // strained pos + batch (bit-cast) per atom
__device__ int    g_is64;            // 1 if edge_index/batch are int64, else int32

// ---------------------------------------------------------------------------
// Kernel 1: per-atom strained position packed with batch into float4.
// Each block redundantly computes sym-strain in smem (cheap, removes a serial
// prep kernel). Block 0 additionally publishes g_cell and g_is64 for kernel 2.
// ---------------------------------------------------------------------------
__global__ void __launch_bounds__(256) atom_kernel(
        const float* __restrict__ pos,
        const void*  __restrict__ batch,
        const void*  __restrict__ eidx,
        const float* __restrict__ strain,
        const float* __restrict__ cell,
        int n_atoms) {
    __shared__ float sS[NB * 9];
    __shared__ int s_is64;
    int tid = threadIdx.x;

    // dtype detection: int64 indices (< 2^31, nonneg) have all-zero odd words.
    if (tid == 0) {
        const unsigned* w = (const unsigned*)eidx;
        unsigned any = 0;
#pragma unroll
        for (int i = 0; i < 64; i++) any |= w[2 * i + 1];
        s_is64 = (any == 0u) ? 1 : 0;
    }
    // sym = 0.5 * (strain + strain^T)
    for (int i = tid; i < NB * 9; i += blockDim.x) {
        int b = i / 9, r = (i % 9) / 3, c = i % 3;
        sS[i] = 0.5f * (strain[b * 9 + r * 3 + c] + strain[b * 9 + c * 3 + r]);
    }
    __syncthreads();

    if (blockIdx.x == 0) {
        // cell_new = cell + cell @ sym  (published for edge kernel)
        for (int i = tid; i < NB * 9; i += blockDim.x) {
            int b = i / 9, r = (i % 9) / 3, c = i % 3;
            float acc = cell[i];
#pragma unroll
            for (int k = 0; k < 3; k++)
                acc += cell[b * 9 + r * 3 + k] * sS[b * 9 + k * 3 + c];
            g_cell[i] = acc;
        }
        if (tid == 0) g_is64 = s_is64;
    }

    int i = blockIdx.x * blockDim.x + tid;
    if (i >= n_atoms) return;

    int b = s_is64 ? (int)((const long long*)batch)[i]
                   : ((const int*)batch)[i];

    float px = pos[3 * i], py = pos[3 * i + 1], pz = pos[3 * i + 2];
    const float* S = &sS[b * 9];
    float nx = px + px * S[0] + py * S[3] + pz * S[6];
    float ny = py + px * S[1] + py * S[4] + pz * S[7];
    float nz = pz + px * S[2] + py * S[5] + pz * S[8];
    g_atom[i] = make_float4(nx, ny, nz, __int_as_float(b));
}

// ---------------------------------------------------------------------------
// Kernel 2: edge vectors + lengths. 4 edges per thread, fully vectorized
// streams with evict-first hints; gathers hit the L2-resident atom table.
// ---------------------------------------------------------------------------
__global__ void __launch_bounds__(256) edge_kernel(
        const void*  __restrict__ eidx,
        const float* __restrict__ cshift,
        float*       __restrict__ out,
        long long E) {
    __shared__ float sC[NB * 9];
    __shared__ int sI;
    if (threadIdx.x == 0) sI = g_is64;
    for (int i = threadIdx.x; i < NB * 9; i += blockDim.x)
        sC[i] = g_cell[i];
    __syncthreads();

    long long t  = (long long)blockIdx.x * blockDim.x + threadIdx.x;
    long long e0 = t << 2;
    if (e0 >= E) return;

    const bool vec_ok = ((E & 3LL) == 0LL);

    if (vec_ok && e0 + 3 < E) {
        long long s[4], d[4];
        if (sI) {
            const longlong2* ps = (const longlong2*)eidx;
            longlong2 a = __ldcs(&ps[2 * t]);
            longlong2 b = __ldcs(&ps[2 * t + 1]);
            const longlong2* pd = (const longlong2*)((const long long*)eidx + E);
            longlong2 c = __ldcs(&pd[2 * t]);
            longlong2 dd = __ldcs(&pd[2 * t + 1]);
            s[0] = a.x; s[1] = a.y; s[2] = b.x; s[3] = b.y;
            d[0] = c.x; d[1] = c.y; d[2] = dd.x; d[3] = dd.y;
        } else {
            const int4* ps = (const int4*)eidx;
            int4 a = __ldcs(&ps[t]);
            const int4* pd = (const int4*)((const int*)eidx + E);
            int4 c = __ldcs(&pd[t]);
            s[0] = a.x; s[1] = a.y; s[2] = a.z; s[3] = a.w;
            d[0] = c.x; d[1] = c.y; d[2] = c.z; d[3] = c.w;
        }

        // 8 independent gathers in flight (L2-resident table)
        float4 A[4], D[4];
#pragma unroll
        for (int i = 0; i < 4; i++) A[i] = __ldg(&g_atom[s[i]]);
#pragma unroll
        for (int i = 0; i < 4; i++) D[i] = __ldg(&g_atom[d[i]]);

        const float4* cs4 = (const float4*)cshift;
        float4 c0 = __ldcs(&cs4[3 * t]);
        float4 c1 = __ldcs(&cs4[3 * t + 1]);
        float4 c2 = __ldcs(&cs4[3 * t + 2]);
        float sh[12] = {c0.x, c0.y, c0.z, c0.w, c1.x, c1.y, c1.z, c1.w,
                        c2.x, c2.y, c2.z, c2.w};

        float vx[4], vy[4], vz[4], ln[4];
#pragma unroll
        for (int i = 0; i < 4; i++) {
            int b = __float_as_int(A[i].w);
            const float* C = &sC[b * 9];
            float s0 = sh[3 * i], s1 = sh[3 * i + 1], s2 = sh[3 * i + 2];
            vx[i] = D[i].x - A[i].x + s0 * C[0] + s1 * C[3] + s2 * C[6];
            vy[i] = D[i].y - A[i].y + s0 * C[1] + s1 * C[4] + s2 * C[7];
            vz[i] = D[i].z - A[i].z + s0 * C[2] + s1 * C[5] + s2 * C[8];
            ln[i] = sqrtf(vx[i] * vx[i] + vy[i] * vy[i] + vz[i] * vz[i]);
        }

        float4* ov = (float4*)out;
        __stcs(&ov[3 * t],     make_float4(vx[0], vy[0], vz[0], vx[1]));
        __stcs(&ov[3 * t + 1], make_float4(vy[1], vz[1], vx[2], vy[2]));
        __stcs(&ov[3 * t + 2], make_float4(vz[2], vx[3], vy[3], vz[3]));
        float4* ol = (float4*)(out + 3 * E);
        __stcs(&ol[t], make_float4(ln[0], ln[1], ln[2], ln[3]));
    } else {
        // scalar fallback (tail / unaligned E)
        for (long long e = e0; e < e0 + 4 && e < E; e++) {
            long long src, dst;
            if (sI) {
                const long long* p = (const long long*)eidx;
                src = p[e]; dst = p[E + e];
            } else {
                const int* p = (const int*)eidx;
                src = p[e]; dst = p[E + e];
            }
            float4 as = __ldg(&g_atom[src]);
            float4 ad = __ldg(&g_atom[dst]);
            int b = __float_as_int(as.w);
            const float* C = &sC[b * 9];
            float s0 = cshift[3 * e], s1 = cshift[3 * e + 1], s2 = cshift[3 * e + 2];
            float ex = ad.x - as.x + s0 * C[0] + s1 * C[3] + s2 * C[6];
            float ey = ad.y - as.y + s0 * C[1] + s1 * C[4] + s2 * C[7];
            float ez = ad.z - as.z + s0 * C[2] + s1 * C[5] + s2 * C[8];
            out[3 * e] = ex; out[3 * e + 1] = ey; out[3 * e + 2] = ez;
            out[3 * E + e] = sqrtf(ex * ex + ey * ey + ez * ez);
        }
    }
}

// ---------------------------------------------------------------------------
extern "C" void kernel_launch(void* const* d_in, const int* in_sizes, int n_in,
                              void* d_out, int out_size) {
    const float* pos    = (const float*)d_in[0];   // [N_ATOMS, 3]
    const float* cell   = (const float*)d_in[1];   // [NB, 3, 3]
    const float* cshift = (const float*)d_in[2];   // [E, 3]
    const void*  eidx   = d_in[3];                 // [2, E] int32 or int64
    const void*  batch  = d_in[4];                 // [N_ATOMS] int32 or int64
    const float* strain = (const float*)d_in[5];   // [NB, 3, 3]

    int n_atoms = in_sizes[0] / 3;
    long long E = (long long)in_sizes[3] / 2;

    int ablocks = (n_atoms + 255) / 256;
    atom_kernel<<<ablocks, 256>>>(pos, batch, eidx, strain, cell, n_atoms);

    long long egroups = (E + 3) / 4;
    int eblocks = (int)((egroups + 255) / 256);
    edge_kernel<<<eblocks, 256>>>(eidx, cshift, (float*)d_out, E);
}